// round 14
// baseline (speedup 1.0000x reference)
#include <cuda_runtime.h>
#include <cuda_bf16.h>
#include <cstdint>
#include <math.h>

// Problem dims (fixed by the dataset)
#define NQ 1024
#define BB 8
#define MM 1024
#define CC 640
#define ROWS 8192                 // NQ*BB == BB*MM
#define LOG2E_OVER_EPS 28.853900817779268f   // log2(e)/0.05
#define SCORE_SCALE 1048576.0f    // M*Nq

// Persistent Sinkhorn config
#define BPB 18
#define NBLK (BB * BPB)
#define ROWCAP 40
#define SK_THREADS 256
#define SK_SMEM_FLOATS (ROWCAP * 1024 + 8 * 1024 + 64)
#define SK_SMEM_BYTES (SK_SMEM_FLOATS * 4 + 64 * 4)

// mma.sync bf16 GEMM: SMEM row stride (bf16 elems), 32-col K chunk + 8 pad
#define APAD 40
#define TILE_E (128 * APAD)               // elems per tile per stage
#define MMA_SMEM_BYTES (2 * 4 * TILE_E * 2)  // 2 stages x 4 arrays x bf16

// ---------------- scratch (static device arrays; no allocation) ----------------
__device__ float g_q[ROWS * CC];
__device__ float g_k[ROWS * CC];
__device__ float g_v[ROWS * CC];
__device__ float g_x[ROWS * CC];
__device__ float g_sim[BB * MM * NQ];
__device__ float g_E[BB * MM * NQ];
__device__ float g_Tc[BB * MM * NQ];    // compacted transport plan
__device__ float g_vc[ROWS * CC];       // compacted V
__device__ float g_part[2][NBLK * NQ];
__device__ float g_mu[BB];
__device__ int   g_rowlist[BB * MM];
__device__ int   g_cnt[BB];
__device__ int   g_mode[1];
__device__ unsigned g_bar_cnt;          // monotonic; reset by init_rows each launch
__device__ float g_attn_sink[ROWS];
__device__ __nv_bfloat16 g_ah[ROWS * CC];
__device__ __nv_bfloat16 g_al[ROWS * CC];
__device__ __nv_bfloat16 g_wh[CC * CC];
__device__ __nv_bfloat16 g_wl[CC * CC];
__device__ __nv_bfloat16 g_qh[ROWS * CC];
__device__ __nv_bfloat16 g_ql[ROWS * CC];
__device__ __nv_bfloat16 g_kh[ROWS * CC];
__device__ __nv_bfloat16 g_kl[ROWS * CC];

// ---------------- helpers ----------------
__device__ __forceinline__ uint32_t smem_u32(const void* p) {
    uint32_t a;
    asm("{ .reg .u64 t; cvta.to.shared.u64 t, %1; cvt.u32.u64 %0, t; }" : "=r"(a) : "l"(p));
    return a;
}
__device__ __forceinline__ void cp_async16(uint32_t saddr, const void* gptr) {
    asm volatile("cp.async.cg.shared.global [%0], [%1], 16;" :: "r"(saddr), "l"(gptr));
}
#define CP_COMMIT() asm volatile("cp.async.commit_group;" ::: "memory")
#define CP_WAIT0()  asm volatile("cp.async.wait_group 0;" ::: "memory")

// ---------------- mask dtype detection ----------------
__global__ void detect_mask_kernel(const unsigned int* __restrict__ m, int* __restrict__ mode)
{
    __shared__ int ok[2];
    if (threadIdx.x == 0) { ok[0] = 1; ok[1] = 1; }
    __syncthreads();
    for (int i = threadIdx.x; i < 2048; i += blockDim.x) {
        unsigned v = m[i];
        if (v > 1u) ok[0] = 0;
        if (v != 0u && v != 0x3F800000u) ok[1] = 0;
    }
    __syncthreads();
    if (threadIdx.x == 0) *mode = ok[0] ? 1 : (ok[1] ? 2 : 0);
}

__device__ __forceinline__ bool mget(const void* mask, int i, int mode)
{
    if (mode == 1) return ((const int*)mask)[i] != 0;
    if (mode == 2) return ((const float*)mask)[i] != 0.0f;
    return ((const unsigned char*)mask)[i] != 0;
}

// ---------------- fp32 -> bf16 hi/lo split ----------------
__global__ void __launch_bounds__(256) split_bf16(
    const float* __restrict__ X, __nv_bfloat16* __restrict__ H,
    __nv_bfloat16* __restrict__ L, int n)
{
    int i = (blockIdx.x * 256 + threadIdx.x) * 4;
    if (i >= n) return;
    float4 v = *(const float4*)(X + i);
    __nv_bfloat16 h0 = __float2bfloat16(v.x);
    __nv_bfloat16 h1 = __float2bfloat16(v.y);
    __nv_bfloat16 h2 = __float2bfloat16(v.z);
    __nv_bfloat16 h3 = __float2bfloat16(v.w);
    __nv_bfloat16 l0 = __float2bfloat16(v.x - __bfloat162float(h0));
    __nv_bfloat16 l1 = __float2bfloat16(v.y - __bfloat162float(h1));
    __nv_bfloat16 l2 = __float2bfloat16(v.z - __bfloat162float(h2));
    __nv_bfloat16 l3 = __float2bfloat16(v.w - __bfloat162float(h3));
    *(__nv_bfloat162*)(H + i)     = __nv_bfloat162(h0, h1);
    *(__nv_bfloat162*)(H + i + 2) = __nv_bfloat162(h2, h3);
    *(__nv_bfloat162*)(L + i)     = __nv_bfloat162(l0, l1);
    *(__nv_bfloat162*)(L + i + 2) = __nv_bfloat162(l2, l3);
}

// ---------------- mma.sync bf16x3 GEMM helpers ----------------
__device__ __forceinline__ void mma16816(float* c, const uint32_t* a, const uint32_t* b)
{
    asm volatile(
        "mma.sync.aligned.m16n8k16.row.col.f32.bf16.bf16.f32 "
        "{%0,%1,%2,%3}, {%4,%5,%6,%7}, {%8,%9}, {%0,%1,%2,%3};"
        : "+f"(c[0]), "+f"(c[1]), "+f"(c[2]), "+f"(c[3])
        : "r"(a[0]), "r"(a[1]), "r"(a[2]), "r"(a[3]), "r"(b[0]), "r"(b[1]));
}

// one 32-wide K chunk of bf16x3 block compute from a given stage's 4 tiles
__device__ __forceinline__ void mma_tile_compute(
    const __nv_bfloat16* __restrict__ Ash, const __nv_bfloat16* __restrict__ Asl,
    const __nv_bfloat16* __restrict__ Bsh, const __nv_bfloat16* __restrict__ Bsl,
    int mw, int nw, int g, int tig, float acc[4][4][4])
{
#pragma unroll
    for (int ks = 0; ks < 2; ks++) {
        uint32_t ah[4][4], al[4][4], bh[4][2], bl[4][2];
#pragma unroll
        for (int ms = 0; ms < 4; ms++) {
            int rr = (mw * 64 + ms * 16 + g) * APAD + ks * 16 + tig * 2;
            ah[ms][0] = *(const uint32_t*)&Ash[rr];
            ah[ms][1] = *(const uint32_t*)&Ash[rr + 8 * APAD];
            ah[ms][2] = *(const uint32_t*)&Ash[rr + 8];
            ah[ms][3] = *(const uint32_t*)&Ash[rr + 8 * APAD + 8];
            al[ms][0] = *(const uint32_t*)&Asl[rr];
            al[ms][1] = *(const uint32_t*)&Asl[rr + 8 * APAD];
            al[ms][2] = *(const uint32_t*)&Asl[rr + 8];
            al[ms][3] = *(const uint32_t*)&Asl[rr + 8 * APAD + 8];
        }
#pragma unroll
        for (int ns = 0; ns < 4; ns++) {
            int rr = (nw * 32 + ns * 8 + g) * APAD + ks * 16 + tig * 2;
            bh[ns][0] = *(const uint32_t*)&Bsh[rr];
            bh[ns][1] = *(const uint32_t*)&Bsh[rr + 8];
            bl[ns][0] = *(const uint32_t*)&Bsl[rr];
            bl[ns][1] = *(const uint32_t*)&Bsl[rr + 8];
        }
#pragma unroll
        for (int ms = 0; ms < 4; ms++)
#pragma unroll
            for (int ns = 0; ns < 4; ns++) {
                mma16816(acc[ms][ns], ah[ms], bh[ns]);
                mma16816(acc[ms][ns], ah[ms], bl[ns]);
                mma16816(acc[ms][ns], al[ms], bh[ns]);
            }
    }
}

// C[r][c] = sum_k A[r][k]*B[c][k] + bias[c]. Block 128x128, 8 warps (2x4).
// 2-stage cp.async double buffer.
__global__ void __launch_bounds__(256) mmagemm_nt_bias(
    const __nv_bfloat16* __restrict__ Ah, const __nv_bfloat16* __restrict__ Al,
    const __nv_bfloat16* __restrict__ Bh, const __nv_bfloat16* __restrict__ Bl,
    const float* __restrict__ bias, float* __restrict__ C)
{
    extern __shared__ __nv_bfloat16 dsm[];
    const uint32_t sb = smem_u32(dsm);
    const int tid = threadIdx.x;
    const int wid = tid >> 5, lane = tid & 31;
    const int g = lane >> 2, tig = lane & 3;
    const int mw = wid >> 2, nw = wid & 3;
    const int row0 = blockIdx.y * 128, col0 = blockIdx.x * 128;
    float acc[4][4][4] = {};

    auto load_stage = [&](int s, int k0) {
#pragma unroll
        for (int t = 0; t < 2; t++) {
            int u = tid + t * 256;
            int r = u >> 2, c8 = (u & 3) * 8;
            uint32_t so = sb + (uint32_t)(s * 4 * TILE_E + r * APAD + c8) * 2;
            cp_async16(so + 0 * TILE_E * 2, Ah + (size_t)(row0 + r) * CC + k0 + c8);
            cp_async16(so + 1 * TILE_E * 2, Al + (size_t)(row0 + r) * CC + k0 + c8);
            cp_async16(so + 2 * TILE_E * 2, Bh + (size_t)(col0 + r) * CC + k0 + c8);
            cp_async16(so + 3 * TILE_E * 2, Bl + (size_t)(col0 + r) * CC + k0 + c8);
        }
    };

    load_stage(0, 0);
    CP_COMMIT(); CP_WAIT0();
    __syncthreads();
    const int NCH = CC / 32;     // 20
    for (int c = 0; c < NCH; c++) {
        const int cur = c & 1;
        if (c + 1 < NCH) { load_stage(cur ^ 1, (c + 1) * 32); CP_COMMIT(); }
        const __nv_bfloat16* base = dsm + cur * 4 * TILE_E;
        mma_tile_compute(base, base + TILE_E, base + 2 * TILE_E, base + 3 * TILE_E,
                         mw, nw, g, tig, acc);
        if (c + 1 < NCH) CP_WAIT0();
        __syncthreads();
    }

#pragma unroll
    for (int ms = 0; ms < 4; ms++) {
        int m = row0 + mw * 64 + ms * 16 + g;
#pragma unroll
        for (int ns = 0; ns < 4; ns++) {
            int n = col0 + nw * 32 + ns * 8 + tig * 2;
            float b0 = bias[n], b1 = bias[n + 1];
            float2 o0 = make_float2(acc[ms][ns][0] + b0, acc[ms][ns][1] + b1);
            float2 o1 = make_float2(acc[ms][ns][2] + b0, acc[ms][ns][3] + b1);
            *(float2*)(C + (size_t)m * CC + n) = o0;
            *(float2*)(C + (size_t)(m + 8) * CC + n) = o1;
        }
    }
}

// sim + E via mma bf16x3, double-buffered. A rows: Kh at (b*MM+m); B rows: Qh at (n*BB+b).
__global__ void __launch_bounds__(256) mmagemm_sim(
    const __nv_bfloat16* __restrict__ Ah, const __nv_bfloat16* __restrict__ Al,
    const __nv_bfloat16* __restrict__ Bh, const __nv_bfloat16* __restrict__ Bl,
    const void* __restrict__ mask, const int* __restrict__ mode,
    float* __restrict__ sim, float* __restrict__ E)
{
    extern __shared__ __nv_bfloat16 dsm[];
    const uint32_t sb = smem_u32(dsm);
    const int tid = threadIdx.x;
    const int wid = tid >> 5, lane = tid & 31;
    const int g = lane >> 2, tig = lane & 3;
    const int mw = wid >> 2, nw = wid & 3;
    const int b = blockIdx.z;
    const int row0 = blockIdx.y * 128, col0 = blockIdx.x * 128;  // row=m, col=n
    float acc[4][4][4] = {};

    auto load_stage = [&](int s, int k0) {
#pragma unroll
        for (int t = 0; t < 2; t++) {
            int u = tid + t * 256;
            int r = u >> 2, c8 = (u & 3) * 8;
            uint32_t so = sb + (uint32_t)(s * 4 * TILE_E + r * APAD + c8) * 2;
            size_t ar = (size_t)((b << 10) + row0 + r) * CC + k0 + c8;
            size_t br = (size_t)((col0 + r) * BB + b) * CC + k0 + c8;
            cp_async16(so + 0 * TILE_E * 2, Ah + ar);
            cp_async16(so + 1 * TILE_E * 2, Al + ar);
            cp_async16(so + 2 * TILE_E * 2, Bh + br);
            cp_async16(so + 3 * TILE_E * 2, Bl + br);
        }
    };

    load_stage(0, 0);
    CP_COMMIT(); CP_WAIT0();
    __syncthreads();
    const int NCH = CC / 32;
    for (int c = 0; c < NCH; c++) {
        const int cur = c & 1;
        if (c + 1 < NCH) { load_stage(cur ^ 1, (c + 1) * 32); CP_COMMIT(); }
        const __nv_bfloat16* base = dsm + cur * 4 * TILE_E;
        mma_tile_compute(base, base + TILE_E, base + 2 * TILE_E, base + 3 * TILE_E,
                         mw, nw, g, tig, acc);
        if (c + 1 < NCH) CP_WAIT0();
        __syncthreads();
    }

    const int md = *mode;
#pragma unroll
    for (int ms = 0; ms < 4; ms++) {
        int m0 = row0 + mw * 64 + ms * 16 + g;
        bool act0 = mget(mask, (b << 10) + m0, md);
        bool act1 = mget(mask, (b << 10) + m0 + 8, md);
#pragma unroll
        for (int ns = 0; ns < 4; ns++) {
            int n = col0 + nw * 32 + ns * 8 + tig * 2;
            size_t i0 = ((size_t)b << 20) + ((size_t)m0 << 10) + n;
            size_t i1 = i0 + (8 << 10);
            float s00 = acc[ms][ns][0], s01 = acc[ms][ns][1];
            float s10 = acc[ms][ns][2], s11 = acc[ms][ns][3];
            *(float2*)(sim + i0) = make_float2(s00, s01);
            *(float2*)(sim + i1) = make_float2(s10, s11);
            float2 e0, e1;
            e0.x = act0 ? exp2f(LOG2E_OVER_EPS * s00) : 0.0f;
            e0.y = act0 ? exp2f(LOG2E_OVER_EPS * s01) : 0.0f;
            e1.x = act1 ? exp2f(LOG2E_OVER_EPS * s10) : 0.0f;
            e1.y = act1 ? exp2f(LOG2E_OVER_EPS * s11) : 0.0f;
            *(float2*)(E + i0) = e0;
            *(float2*)(E + i1) = e1;
        }
    }
}

// ---------------- fp32 GEMM: x[n][c] = sum_i Tc[b][i][n] * Vc[b][i][c] ----------------
// K-loop over COMPACTED active rows only (cnt_pad = round32(cnt)); exact zeros dropped.
#define BMT 128
#define BNT 128
#define BKT 32

__global__ void __launch_bounds__(256, 2) gemm_tn_x(
    const float* __restrict__ Tc, const float* __restrict__ Vc,
    const int* __restrict__ cntv, float* __restrict__ X)
{
    __shared__ float As[BKT][BMT];
    __shared__ float Bs[BKT][BNT];
    const int tid = threadIdx.x;
    const int tx = tid & 15, ty = tid >> 4;
    const int b = blockIdx.z;
    const int n0 = blockIdx.y * BMT, c0 = blockIdx.x * BNT;
    const int cnt_pad = (cntv[b] + 31) & ~31;
    const float* Tb = Tc + ((size_t)b << 20);
    const float* Vb = Vc + (size_t)b * MM * CC;
    float acc[8][8] = {};
    for (int m0 = 0; m0 < cnt_pad; m0 += BKT) {
#pragma unroll
        for (int j = 0; j < 4; j++) {
            int idx = tid * 4 + j;
            int mr = idx >> 5, c4 = idx & 31;
            *(float4*)&As[mr][c4 * 4] = *(const float4*)(Tb + (size_t)(m0 + mr) * NQ + n0 + c4 * 4);
        }
#pragma unroll
        for (int j = 0; j < 4; j++) {
            int idx = tid * 4 + j;
            int mr = idx >> 5, c4 = idx & 31;
            *(float4*)&Bs[mr][c4 * 4] = *(const float4*)(Vb + (size_t)(m0 + mr) * CC + c0 + c4 * 4);
        }
        __syncthreads();
#pragma unroll
        for (int kk = 0; kk < BKT; kk++) {
            float a[8], bb[8];
            *(float4*)a        = *(const float4*)&As[kk][ty * 8];
            *(float4*)(a + 4)  = *(const float4*)&As[kk][ty * 8 + 4];
            *(float4*)bb       = *(const float4*)&Bs[kk][tx * 8];
            *(float4*)(bb + 4) = *(const float4*)&Bs[kk][tx * 8 + 4];
#pragma unroll
            for (int i = 0; i < 8; i++)
#pragma unroll
                for (int jj = 0; jj < 8; jj++)
                    acc[i][jj] = fmaf(a[i], bb[jj], acc[i][jj]);
        }
        __syncthreads();
    }
#pragma unroll
    for (int i = 0; i < 8; i++) {
        int n = n0 + ty * 8 + i;
        float* xr = X + (size_t)(n * BB + b) * CC + c0 + tx * 8;
        float4 o0, o1;
        o0.x = acc[i][0]; o0.y = acc[i][1]; o0.z = acc[i][2]; o0.w = acc[i][3];
        o1.x = acc[i][4]; o1.y = acc[i][5]; o1.z = acc[i][6]; o1.w = acc[i][7];
        *(float4*)xr = o0; *(float4*)(xr + 4) = o1;
    }
}

// ---------------- small kernels ----------------
__global__ void __launch_bounds__(128) l2norm_split(
    const float* __restrict__ X, __nv_bfloat16* __restrict__ H, __nv_bfloat16* __restrict__ L)
{
    const int r = blockIdx.x;
    const float* row = X + (size_t)r * CC;
    float v[5];
    float ss = 0.0f;
#pragma unroll
    for (int i = 0; i < 5; i++) { v[i] = row[threadIdx.x + i * 128]; ss = fmaf(v[i], v[i], ss); }
    for (int o = 16; o; o >>= 1) ss += __shfl_down_sync(0xffffffffu, ss, o);
    __shared__ float ws[4];
    if ((threadIdx.x & 31) == 0) ws[threadIdx.x >> 5] = ss;
    __syncthreads();
    float tot = ws[0] + ws[1] + ws[2] + ws[3];
    float inv = 1.0f / fmaxf(sqrtf(tot), 1e-12f);
#pragma unroll
    for (int i = 0; i < 5; i++) {
        float y = v[i] * inv;
        __nv_bfloat16 h = __float2bfloat16(y);
        __nv_bfloat16 l = __float2bfloat16(y - __bfloat162float(h));
        H[(size_t)r * CC + threadIdx.x + i * 128] = h;
        L[(size_t)r * CC + threadIdx.x + i * 128] = l;
    }
}

// compact active rows, counts, mu; zero attn; reset barrier; zero Tc/Vc pad rows.
__global__ void __launch_bounds__(256) init_rows(
    const void* __restrict__ mask, const int* __restrict__ mode,
    int* __restrict__ rowlist, int* __restrict__ cnt,
    float* __restrict__ mu, float* __restrict__ attn_out,
    float* __restrict__ Tc, float* __restrict__ Vc)
{
    const int w = threadIdx.x >> 5, lane = threadIdx.x & 31;
    const int md = *mode;
    const int b = w;
    int base = 0;
    for (int c = 0; c < 32; c++) {
        int m = c * 32 + lane;
        bool act = mget(mask, (b << 10) + m, md);
        unsigned bal = __ballot_sync(0xffffffffu, act);
        int pre = __popc(bal & ((1u << lane) - 1u));
        if (act) rowlist[(b << 10) + base + pre] = m;
        base += __popc(bal);
    }
    if (lane == 0) {
        cnt[b] = base;
        int cm = base > 1 ? base : 1;
        mu[b] = 1.0f / (float)cm + 1e-8f;
    }
    // zero pad rows [cnt, round32(cnt)) of Tc and Vc for this batch
    {
        int cpad = (base + 31) & ~31;
        for (int rr = base; rr < cpad && rr < MM; rr++) {
            float* tr = Tc + ((size_t)(b * MM + rr) << 10);
            for (int c = lane; c < NQ; c += 32) tr[c] = 0.0f;
            float* vr = Vc + (size_t)(b * MM + rr) * CC;
            for (int c = lane; c < CC; c += 32) vr[c] = 0.0f;
        }
    }
    if (threadIdx.x == 0) g_bar_cnt = 0u;
    for (int i = threadIdx.x; i < ROWS; i += 256) attn_out[i] = 0.0f;
}

// Vc[b][i][:] = V[b][rowlist[b][i]][:]
__global__ void __launch_bounds__(128) gather_v(
    const float* __restrict__ V, const int* __restrict__ rowlist,
    const int* __restrict__ cntv, float* __restrict__ Vc)
{
    const int idx = blockIdx.x;
    const int b = idx >> 10, i = idx & 1023;
    if (i >= cntv[b]) return;
    const int m = rowlist[(b << 10) + i];
    const float4* src = (const float4*)(V + (size_t)(b * MM + m) * CC);
    float4* dst = (float4*)(Vc + (size_t)(b * MM + i) * CC);
    for (int t = threadIdx.x; t < CC / 4; t += 128) dst[t] = src[t];
}

// ---------------- persistent Sinkhorn ----------------
__device__ __forceinline__ void gridbar(int tid, unsigned epoch)
{
    __syncthreads();
    if (tid == 0) {
        __threadfence();
        atomicAdd(&g_bar_cnt, 1u);
        const unsigned tgt = (unsigned)NBLK * epoch;
        while (*(volatile unsigned*)&g_bar_cnt < tgt) __nanosleep(32);
        __threadfence();
    }
    __syncthreads();
}

__global__ void __launch_bounds__(SK_THREADS, 1) sk_persist(
    const float* __restrict__ E, const float* __restrict__ sim,
    float* __restrict__ Tc, float* __restrict__ attn_out, float nu_eff)
{
    extern __shared__ float smemf[];
    float* e_s   = smemf;
    float* acc_s = smemf + ROWCAP * 1024;
    float* a_s   = acc_s + 8 * 1024;
    int*   rows_s = (int*)(a_s + 64);

    const int tid = threadIdx.x;
    const int w = tid >> 5, lane = tid & 31;
    const int b = blockIdx.x / BPB;
    const int j = blockIdx.x % BPB;
    const int cnt = g_cnt[b];
    const int r0 = j * cnt / BPB;
    const int r1 = (j + 1) * cnt / BPB;
    const int nrows = r1 - r0;
    const int ncache = nrows < ROWCAP ? nrows : ROWCAP;
    const float mub = g_mu[b];

    for (int i = tid; i < nrows; i += SK_THREADS)
        rows_s[i] = g_rowlist[(b << 10) + r0 + i];
    __syncthreads();

    for (int i = 0; i < ncache; i++) {
        const float4* src = (const float4*)(E + ((size_t)b << 20) + ((size_t)rows_s[i] << 10));
        float4* dst = (float4*)(e_s + i * 1024);
        for (int t = tid; t < 256; t += SK_THREADS) dst[t] = __ldg(src + t);
    }
    __syncthreads();

    float4 bvreg[8];
#pragma unroll
    for (int t = 0; t < 8; t++) bvreg[t] = make_float4(1.f, 1.f, 1.f, 1.f);

    for (int it = 0; it < 100; it++) {
        const int par = it & 1;
        float4 cacc[8] = {};
        for (int i = w; i < nrows; i += 8) {
            const float4* er = (i < ncache)
                ? (const float4*)(e_s + i * 1024)
                : (const float4*)(E + ((size_t)b << 20) + ((size_t)rows_s[i] << 10));
            float4 e[8];
            float s = 0.0f;
#pragma unroll
            for (int t = 0; t < 8; t++) {
                e[t] = er[t * 32 + lane];
                s = fmaf(e[t].x, bvreg[t].x, s); s = fmaf(e[t].y, bvreg[t].y, s);
                s = fmaf(e[t].z, bvreg[t].z, s); s = fmaf(e[t].w, bvreg[t].w, s);
            }
#pragma unroll
            for (int o = 16; o; o >>= 1) s += __shfl_xor_sync(0xffffffffu, s, o);
            float av = (s > 0.0f) ? mub / s : 0.0f;
            if (lane == 0) a_s[i] = av;
#pragma unroll
            for (int t = 0; t < 8; t++) {
                cacc[t].x = fmaf(av, e[t].x, cacc[t].x);
                cacc[t].y = fmaf(av, e[t].y, cacc[t].y);
                cacc[t].z = fmaf(av, e[t].z, cacc[t].z);
                cacc[t].w = fmaf(av, e[t].w, cacc[t].w);
            }
        }
#pragma unroll
        for (int t = 0; t < 8; t++)
            *(float4*)&acc_s[w * 1024 + t * 128 + lane * 4] = cacc[t];
        __syncthreads();
        {
            float4 ssum = *(const float4*)&acc_s[tid * 4];
#pragma unroll
            for (int ww = 1; ww < 8; ww++) {
                float4 v = *(const float4*)&acc_s[ww * 1024 + tid * 4];
                ssum.x += v.x; ssum.y += v.y; ssum.z += v.z; ssum.w += v.w;
            }
            *(float4*)&g_part[par][(size_t)blockIdx.x * 1024 + tid * 4] = ssum;
        }
        gridbar(tid, (unsigned)(it + 1));
        {
            const float* pp = &g_part[par][(size_t)(b * BPB) * 1024];
            const int c4 = tid * 4;
            float4 c = __ldcg((const float4*)(pp + c4));
#pragma unroll
            for (int jj = 1; jj < BPB; jj++) {
                float4 v = __ldcg((const float4*)(pp + jj * 1024 + c4));
                c.x += v.x; c.y += v.y; c.z += v.z; c.w += v.w;
            }
            float4 bv4;
            bv4.x = (c.x > 0.0f) ? nu_eff / c.x : 0.0f;
            bv4.y = (c.y > 0.0f) ? nu_eff / c.y : 0.0f;
            bv4.z = (c.z > 0.0f) ? nu_eff / c.z : 0.0f;
            bv4.w = (c.w > 0.0f) ? nu_eff / c.w : 0.0f;
            *(float4*)&acc_s[c4] = bv4;
        }
        __syncthreads();
#pragma unroll
        for (int t = 0; t < 8; t++)
            bvreg[t] = *(const float4*)&acc_s[t * 128 + lane * 4];
        __syncthreads();
    }

    // finalize: write COMPACTED T (slot = r0+i) and attn (by original row m)
    for (int i = w; i < nrows; i += 8) {
        const int m = rows_s[i];
        const size_t sbase = ((size_t)b << 20) + ((size_t)m << 10);
        const float av = a_s[i];
        const float4* er = (i < ncache)
            ? (const float4*)(e_s + i * 1024)
            : (const float4*)(E + sbase);
        const float4* sr = (const float4*)(sim + sbase);
        float4* tw = (float4*)(Tc + ((size_t)(b * MM + r0 + i) << 10));
        float s = 0.0f;
#pragma unroll
        for (int t = 0; t < 8; t++) {
            float4 e = er[t * 32 + lane];
            float4 bb = bvreg[t];
            float4 T4;
            T4.x = av * e.x * bb.x; T4.y = av * e.y * bb.y;
            T4.z = av * e.z * bb.z; T4.w = av * e.w * bb.w;
            tw[t * 32 + lane] = T4;
            float4 sv = __ldg(sr + t * 32 + lane);
            s = fmaf(sv.x, T4.x, s); s = fmaf(sv.y, T4.y, s);
            s = fmaf(sv.z, T4.z, s); s = fmaf(sv.w, T4.w, s);
        }
#pragma unroll
        for (int o = 16; o; o >>= 1) s += __shfl_xor_sync(0xffffffffu, s, o);
        if (lane == 0) attn_out[(b << 10) + m] = SCORE_SCALE * s;
    }
}

// ---------------- launch ----------------
extern "C" void kernel_launch(void* const* d_in, const int* in_sizes, int n_in,
                              void* d_out, int out_size)
{
    const float* xq = (const float*)d_in[0];
    const float* xk = (const float*)d_in[1];
    const float* xv = (const float*)d_in[2];
    const void*  mask = d_in[3];
    const float* Wq = (const float*)d_in[4];
    const float* bq = (const float*)d_in[5];
    const float* Wk = (const float*)d_in[6];
    const float* bk = (const float*)d_in[7];
    const float* Wv = (const float*)d_in[8];
    const float* bv_in = (const float*)d_in[9];
    const float* Wp = (const float*)d_in[10];
    const float* bp = (const float*)d_in[11];
    float* out = (float*)d_out;

    float *p_q, *p_k, *p_v, *p_x, *p_sim, *p_E, *p_Tc, *p_vc, *p_mu, *p_sink;
    int *p_mode, *p_rows, *p_cnt;
    __nv_bfloat16 *p_ah, *p_al, *p_wh, *p_wl, *p_qh, *p_ql, *p_kh, *p_kl;
    cudaGetSymbolAddress((void**)&p_q, g_q);
    cudaGetSymbolAddress((void**)&p_k, g_k);
    cudaGetSymbolAddress((void**)&p_v, g_v);
    cudaGetSymbolAddress((void**)&p_x, g_x);
    cudaGetSymbolAddress((void**)&p_sim, g_sim);
    cudaGetSymbolAddress((void**)&p_E, g_E);
    cudaGetSymbolAddress((void**)&p_Tc, g_Tc);
    cudaGetSymbolAddress((void**)&p_vc, g_vc);
    cudaGetSymbolAddress((void**)&p_mu, g_mu);
    cudaGetSymbolAddress((void**)&p_sink, g_attn_sink);
    cudaGetSymbolAddress((void**)&p_mode, g_mode);
    cudaGetSymbolAddress((void**)&p_rows, g_rowlist);
    cudaGetSymbolAddress((void**)&p_cnt, g_cnt);
    cudaGetSymbolAddress((void**)&p_ah, g_ah);
    cudaGetSymbolAddress((void**)&p_al, g_al);
    cudaGetSymbolAddress((void**)&p_wh, g_wh);
    cudaGetSymbolAddress((void**)&p_wl, g_wl);
    cudaGetSymbolAddress((void**)&p_qh, g_qh);
    cudaGetSymbolAddress((void**)&p_ql, g_ql);
    cudaGetSymbolAddress((void**)&p_kh, g_kh);
    cudaGetSymbolAddress((void**)&p_kl, g_kl);

    cudaFuncSetAttribute(sk_persist, cudaFuncAttributeMaxDynamicSharedMemorySize, SK_SMEM_BYTES);
    cudaFuncSetAttribute(mmagemm_nt_bias, cudaFuncAttributeMaxDynamicSharedMemorySize, MMA_SMEM_BYTES);
    cudaFuncSetAttribute(mmagemm_sim, cudaFuncAttributeMaxDynamicSharedMemorySize, MMA_SMEM_BYTES);

    float* attn_out = (out_size >= NQ * BB * CC + BB * MM) ? (out + NQ * BB * CC) : p_sink;

    detect_mask_kernel<<<1, 256>>>((const unsigned int*)mask, p_mode);

    const int NA = ROWS * CC;          // 5,242,880
    const int NW = CC * CC;            // 409,600
    dim3 gbf(CC / 128, ROWS / 128);    // (5, 64)

    // Q projection
    split_bf16<<<NA / 1024, 256>>>(xq, p_ah, p_al, NA);
    split_bf16<<<NW / 1024, 256>>>(Wq, p_wh, p_wl, NW);
    mmagemm_nt_bias<<<gbf, 256, MMA_SMEM_BYTES>>>(p_ah, p_al, p_wh, p_wl, bq, p_q);
    // K projection
    split_bf16<<<NA / 1024, 256>>>(xk, p_ah, p_al, NA);
    split_bf16<<<NW / 1024, 256>>>(Wk, p_wh, p_wl, NW);
    mmagemm_nt_bias<<<gbf, 256, MMA_SMEM_BYTES>>>(p_ah, p_al, p_wh, p_wl, bk, p_k);
    // V projection
    split_bf16<<<NA / 1024, 256>>>(xv, p_ah, p_al, NA);
    split_bf16<<<NW / 1024, 256>>>(Wv, p_wh, p_wl, NW);
    mmagemm_nt_bias<<<gbf, 256, MMA_SMEM_BYTES>>>(p_ah, p_al, p_wh, p_wl, bv_in, p_v);

    // normalize + split q/k to bf16 hi/lo
    l2norm_split<<<ROWS, 128>>>(p_q, p_qh, p_ql);
    l2norm_split<<<ROWS, 128>>>(p_k, p_kh, p_kl);

    init_rows<<<1, 256>>>(mask, p_mode, p_rows, p_cnt, p_mu, attn_out, p_Tc, p_vc);
    gather_v<<<ROWS, 128>>>(p_v, p_rows, p_cnt, p_vc);

    dim3 gsim(NQ / 128, MM / 128, BB);  // (8, 8, 8)
    mmagemm_sim<<<gsim, 256, MMA_SMEM_BYTES>>>(p_kh, p_kl, p_qh, p_ql, mask, p_mode, p_sim, p_E);

    const float nu_eff = 1.0f / (float)NQ + 1e-8f;
    sk_persist<<<NBLK, SK_THREADS, SK_SMEM_BYTES>>>(p_E, p_sim, p_Tc, attn_out, nu_eff);

    dim3 gx(CC / BNT, NQ / BMT, BB);    // (5, 8, 8)
    gemm_tn_x<<<gx, 256>>>(p_Tc, p_vc, p_cnt, p_x);

    // output projection
    split_bf16<<<NA / 1024, 256>>>(p_x, p_ah, p_al, NA);
    split_bf16<<<NW / 1024, 256>>>(Wp, p_wh, p_wl, NW);
    mmagemm_nt_bias<<<gbf, 256, MMA_SMEM_BYTES>>>(p_ah, p_al, p_wh, p_wl, bp, out);
}

// round 15
// speedup vs baseline: 1.5046x; 1.5046x over previous
#include <cuda_runtime.h>
#include <cuda_bf16.h>
#include <cstdint>
#include <math.h>

// Problem dims (fixed by the dataset)
#define NQ 1024
#define BB 8
#define MM 1024
#define CC 640
#define ROWS 8192                 // NQ*BB == BB*MM
#define LOG2E_OVER_EPS 28.853900817779268f   // log2(e)/0.05
#define SCORE_SCALE 1048576.0f    // M*Nq

// Persistent Sinkhorn config
#define BPB 18
#define NBLK (BB * BPB)
#define ROWCAP 40
#define SK_THREADS 256
#define SK_SMEM_FLOATS (ROWCAP * 1024 + 8 * 1024 + 64)
#define SK_SMEM_BYTES (SK_SMEM_FLOATS * 4 + 64 * 4)

// mma.sync bf16 GEMM: SMEM row stride (bf16 elems), 32-col K chunk + 8 pad
#define APAD 40

// ---------------- scratch (static device arrays; no allocation) ----------------
__device__ float g_q[ROWS * CC];
__device__ float g_k[ROWS * CC];
__device__ float g_v[ROWS * CC];
__device__ float g_x[ROWS * CC];
__device__ float g_sim[BB * MM * NQ];
__device__ float g_E[BB * MM * NQ];
__device__ float g_Tc[BB * MM * NQ];    // compacted transport plan
__device__ float g_vc[ROWS * CC];       // compacted V
__device__ float g_part[2][NBLK * NQ];
__device__ float g_mu[BB];
__device__ int   g_rowlist[BB * MM];
__device__ int   g_cnt[BB];
__device__ int   g_mode[1];
__device__ unsigned g_bar_cnt;          // monotonic; reset by init_rows each launch
__device__ float g_attn_sink[ROWS];
__device__ __nv_bfloat16 g_ah[ROWS * CC];
__device__ __nv_bfloat16 g_al[ROWS * CC];
__device__ __nv_bfloat16 g_wh[CC * CC];
__device__ __nv_bfloat16 g_wl[CC * CC];
__device__ __nv_bfloat16 g_qh[ROWS * CC];
__device__ __nv_bfloat16 g_ql[ROWS * CC];
__device__ __nv_bfloat16 g_kh[ROWS * CC];
__device__ __nv_bfloat16 g_kl[ROWS * CC];

// ---------------- mask dtype detection ----------------
__global__ void detect_mask_kernel(const unsigned int* __restrict__ m, int* __restrict__ mode)
{
    __shared__ int ok[2];
    if (threadIdx.x == 0) { ok[0] = 1; ok[1] = 1; }
    __syncthreads();
    for (int i = threadIdx.x; i < 2048; i += blockDim.x) {
        unsigned v = m[i];
        if (v > 1u) ok[0] = 0;
        if (v != 0u && v != 0x3F800000u) ok[1] = 0;
    }
    __syncthreads();
    if (threadIdx.x == 0) *mode = ok[0] ? 1 : (ok[1] ? 2 : 0);
}

__device__ __forceinline__ bool mget(const void* mask, int i, int mode)
{
    if (mode == 1) return ((const int*)mask)[i] != 0;
    if (mode == 2) return ((const float*)mask)[i] != 0.0f;
    return ((const unsigned char*)mask)[i] != 0;
}

// ---------------- fp32 -> bf16 hi/lo split ----------------
__global__ void __launch_bounds__(256) split_bf16(
    const float* __restrict__ X, __nv_bfloat16* __restrict__ H,
    __nv_bfloat16* __restrict__ L, int n)
{
    int i = (blockIdx.x * 256 + threadIdx.x) * 4;
    if (i >= n) return;
    float4 v = *(const float4*)(X + i);
    __nv_bfloat16 h0 = __float2bfloat16(v.x);
    __nv_bfloat16 h1 = __float2bfloat16(v.y);
    __nv_bfloat16 h2 = __float2bfloat16(v.z);
    __nv_bfloat16 h3 = __float2bfloat16(v.w);
    __nv_bfloat16 l0 = __float2bfloat16(v.x - __bfloat162float(h0));
    __nv_bfloat16 l1 = __float2bfloat16(v.y - __bfloat162float(h1));
    __nv_bfloat16 l2 = __float2bfloat16(v.z - __bfloat162float(h2));
    __nv_bfloat16 l3 = __float2bfloat16(v.w - __bfloat162float(h3));
    *(__nv_bfloat162*)(H + i)     = __nv_bfloat162(h0, h1);
    *(__nv_bfloat162*)(H + i + 2) = __nv_bfloat162(h2, h3);
    *(__nv_bfloat162*)(L + i)     = __nv_bfloat162(l0, l1);
    *(__nv_bfloat162*)(L + i + 2) = __nv_bfloat162(l2, l3);
}

// ---------------- mma.sync bf16x3 GEMM helpers ----------------
__device__ __forceinline__ void mma16816(float* c, const uint32_t* a, const uint32_t* b)
{
    asm volatile(
        "mma.sync.aligned.m16n8k16.row.col.f32.bf16.bf16.f32 "
        "{%0,%1,%2,%3}, {%4,%5,%6,%7}, {%8,%9}, {%0,%1,%2,%3};"
        : "+f"(c[0]), "+f"(c[1]), "+f"(c[2]), "+f"(c[3])
        : "r"(a[0]), "r"(a[1]), "r"(a[2]), "r"(a[3]), "r"(b[0]), "r"(b[1]));
}

// C[r][c] = sum_k A[r][k]*B[c][k] + bias[c]. Block 128x128, 8 warps (2x4).
// Static SMEM (41KB -> 2 CTAs/SM); R12-verified 104us version.
__global__ void __launch_bounds__(256) mmagemm_nt_bias(
    const __nv_bfloat16* __restrict__ Ah, const __nv_bfloat16* __restrict__ Al,
    const __nv_bfloat16* __restrict__ Bh, const __nv_bfloat16* __restrict__ Bl,
    const float* __restrict__ bias, float* __restrict__ C)
{
    __shared__ __nv_bfloat16 Ash[128 * APAD], Asl[128 * APAD];
    __shared__ __nv_bfloat16 Bsh[128 * APAD], Bsl[128 * APAD];
    const int tid = threadIdx.x;
    const int wid = tid >> 5, lane = tid & 31;
    const int g = lane >> 2, tig = lane & 3;
    const int mw = wid >> 2, nw = wid & 3;
    const int row0 = blockIdx.y * 128, col0 = blockIdx.x * 128;
    float acc[4][4][4] = {};

    for (int k0 = 0; k0 < CC; k0 += 32) {
#pragma unroll
        for (int t = 0; t < 2; t++) {
            int u = tid + t * 256;
            int r = u >> 2, c8 = (u & 3) * 8;
            *(float4*)&Ash[r * APAD + c8] = *(const float4*)(Ah + (size_t)(row0 + r) * CC + k0 + c8);
            *(float4*)&Asl[r * APAD + c8] = *(const float4*)(Al + (size_t)(row0 + r) * CC + k0 + c8);
            *(float4*)&Bsh[r * APAD + c8] = *(const float4*)(Bh + (size_t)(col0 + r) * CC + k0 + c8);
            *(float4*)&Bsl[r * APAD + c8] = *(const float4*)(Bl + (size_t)(col0 + r) * CC + k0 + c8);
        }
        __syncthreads();
#pragma unroll
        for (int ks = 0; ks < 2; ks++) {
            uint32_t ah[4][4], al[4][4], bh[4][2], bl[4][2];
#pragma unroll
            for (int ms = 0; ms < 4; ms++) {
                int rr = (mw * 64 + ms * 16 + g) * APAD + ks * 16 + tig * 2;
                ah[ms][0] = *(const uint32_t*)&Ash[rr];
                ah[ms][1] = *(const uint32_t*)&Ash[rr + 8 * APAD];
                ah[ms][2] = *(const uint32_t*)&Ash[rr + 8];
                ah[ms][3] = *(const uint32_t*)&Ash[rr + 8 * APAD + 8];
                al[ms][0] = *(const uint32_t*)&Asl[rr];
                al[ms][1] = *(const uint32_t*)&Asl[rr + 8 * APAD];
                al[ms][2] = *(const uint32_t*)&Asl[rr + 8];
                al[ms][3] = *(const uint32_t*)&Asl[rr + 8 * APAD + 8];
            }
#pragma unroll
            for (int ns = 0; ns < 4; ns++) {
                int rr = (nw * 32 + ns * 8 + g) * APAD + ks * 16 + tig * 2;
                bh[ns][0] = *(const uint32_t*)&Bsh[rr];
                bh[ns][1] = *(const uint32_t*)&Bsh[rr + 8];
                bl[ns][0] = *(const uint32_t*)&Bsl[rr];
                bl[ns][1] = *(const uint32_t*)&Bsl[rr + 8];
            }
#pragma unroll
            for (int ms = 0; ms < 4; ms++)
#pragma unroll
                for (int ns = 0; ns < 4; ns++) {
                    mma16816(acc[ms][ns], ah[ms], bh[ns]);
                    mma16816(acc[ms][ns], ah[ms], bl[ns]);
                    mma16816(acc[ms][ns], al[ms], bh[ns]);
                }
        }
        __syncthreads();
    }

#pragma unroll
    for (int ms = 0; ms < 4; ms++) {
        int m = row0 + mw * 64 + ms * 16 + g;
#pragma unroll
        for (int ns = 0; ns < 4; ns++) {
            int n = col0 + nw * 32 + ns * 8 + tig * 2;
            float b0 = bias[n], b1 = bias[n + 1];
            float2 o0 = make_float2(acc[ms][ns][0] + b0, acc[ms][ns][1] + b1);
            float2 o1 = make_float2(acc[ms][ns][2] + b0, acc[ms][ns][3] + b1);
            *(float2*)(C + (size_t)m * CC + n) = o0;
            *(float2*)(C + (size_t)(m + 8) * CC + n) = o1;
        }
    }
}

// sim + E via mma bf16x3 (R12-verified). A rows: Kh at (b*MM+m); B rows: Qh at (n*BB+b).
__global__ void __launch_bounds__(256) mmagemm_sim(
    const __nv_bfloat16* __restrict__ Ah, const __nv_bfloat16* __restrict__ Al,
    const __nv_bfloat16* __restrict__ Bh, const __nv_bfloat16* __restrict__ Bl,
    const void* __restrict__ mask, const int* __restrict__ mode,
    float* __restrict__ sim, float* __restrict__ E)
{
    __shared__ __nv_bfloat16 Ash[128 * APAD], Asl[128 * APAD];
    __shared__ __nv_bfloat16 Bsh[128 * APAD], Bsl[128 * APAD];
    const int tid = threadIdx.x;
    const int wid = tid >> 5, lane = tid & 31;
    const int g = lane >> 2, tig = lane & 3;
    const int mw = wid >> 2, nw = wid & 3;
    const int b = blockIdx.z;
    const int row0 = blockIdx.y * 128, col0 = blockIdx.x * 128;  // row=m, col=n
    float acc[4][4][4] = {};

    for (int k0 = 0; k0 < CC; k0 += 32) {
#pragma unroll
        for (int t = 0; t < 2; t++) {
            int u = tid + t * 256;
            int r = u >> 2, c8 = (u & 3) * 8;
            size_t ar = (size_t)((b << 10) + row0 + r) * CC + k0 + c8;
            size_t br = (size_t)((col0 + r) * BB + b) * CC + k0 + c8;
            *(float4*)&Ash[r * APAD + c8] = *(const float4*)(Ah + ar);
            *(float4*)&Asl[r * APAD + c8] = *(const float4*)(Al + ar);
            *(float4*)&Bsh[r * APAD + c8] = *(const float4*)(Bh + br);
            *(float4*)&Bsl[r * APAD + c8] = *(const float4*)(Bl + br);
        }
        __syncthreads();
#pragma unroll
        for (int ks = 0; ks < 2; ks++) {
            uint32_t ah[4][4], al[4][4], bh[4][2], bl[4][2];
#pragma unroll
            for (int ms = 0; ms < 4; ms++) {
                int rr = (mw * 64 + ms * 16 + g) * APAD + ks * 16 + tig * 2;
                ah[ms][0] = *(const uint32_t*)&Ash[rr];
                ah[ms][1] = *(const uint32_t*)&Ash[rr + 8 * APAD];
                ah[ms][2] = *(const uint32_t*)&Ash[rr + 8];
                ah[ms][3] = *(const uint32_t*)&Ash[rr + 8 * APAD + 8];
                al[ms][0] = *(const uint32_t*)&Asl[rr];
                al[ms][1] = *(const uint32_t*)&Asl[rr + 8 * APAD];
                al[ms][2] = *(const uint32_t*)&Asl[rr + 8];
                al[ms][3] = *(const uint32_t*)&Asl[rr + 8 * APAD + 8];
            }
#pragma unroll
            for (int ns = 0; ns < 4; ns++) {
                int rr = (nw * 32 + ns * 8 + g) * APAD + ks * 16 + tig * 2;
                bh[ns][0] = *(const uint32_t*)&Bsh[rr];
                bh[ns][1] = *(const uint32_t*)&Bsh[rr + 8];
                bl[ns][0] = *(const uint32_t*)&Bsl[rr];
                bl[ns][1] = *(const uint32_t*)&Bsl[rr + 8];
            }
#pragma unroll
            for (int ms = 0; ms < 4; ms++)
#pragma unroll
                for (int ns = 0; ns < 4; ns++) {
                    mma16816(acc[ms][ns], ah[ms], bh[ns]);
                    mma16816(acc[ms][ns], ah[ms], bl[ns]);
                    mma16816(acc[ms][ns], al[ms], bh[ns]);
                }
        }
        __syncthreads();
    }

    const int md = *mode;
#pragma unroll
    for (int ms = 0; ms < 4; ms++) {
        int m0 = row0 + mw * 64 + ms * 16 + g;
        bool act0 = mget(mask, (b << 10) + m0, md);
        bool act1 = mget(mask, (b << 10) + m0 + 8, md);
#pragma unroll
        for (int ns = 0; ns < 4; ns++) {
            int n = col0 + nw * 32 + ns * 8 + tig * 2;
            size_t i0 = ((size_t)b << 20) + ((size_t)m0 << 10) + n;
            size_t i1 = i0 + (8 << 10);
            float s00 = acc[ms][ns][0], s01 = acc[ms][ns][1];
            float s10 = acc[ms][ns][2], s11 = acc[ms][ns][3];
            *(float2*)(sim + i0) = make_float2(s00, s01);
            *(float2*)(sim + i1) = make_float2(s10, s11);
            float2 e0, e1;
            e0.x = act0 ? exp2f(LOG2E_OVER_EPS * s00) : 0.0f;
            e0.y = act0 ? exp2f(LOG2E_OVER_EPS * s01) : 0.0f;
            e1.x = act1 ? exp2f(LOG2E_OVER_EPS * s10) : 0.0f;
            e1.y = act1 ? exp2f(LOG2E_OVER_EPS * s11) : 0.0f;
            *(float2*)(E + i0) = e0;
            *(float2*)(E + i1) = e1;
        }
    }
}

// ---------------- fp32 GEMM: x[n][c] = sum_i Tc[b][i][n] * Vc[b][i][c] ----------------
// K-loop over COMPACTED active rows only (cnt_pad = round32(cnt)); exact zeros dropped.
#define BMT 128
#define BNT 128
#define BKT 32

__global__ void __launch_bounds__(256, 2) gemm_tn_x(
    const float* __restrict__ Tc, const float* __restrict__ Vc,
    const int* __restrict__ cntv, float* __restrict__ X)
{
    __shared__ float As[BKT][BMT];
    __shared__ float Bs[BKT][BNT];
    const int tid = threadIdx.x;
    const int tx = tid & 15, ty = tid >> 4;
    const int b = blockIdx.z;
    const int n0 = blockIdx.y * BMT, c0 = blockIdx.x * BNT;
    const int cnt_pad = (cntv[b] + 31) & ~31;
    const float* Tb = Tc + ((size_t)b << 20);
    const float* Vb = Vc + (size_t)b * MM * CC;
    float acc[8][8] = {};
    for (int m0 = 0; m0 < cnt_pad; m0 += BKT) {
#pragma unroll
        for (int j = 0; j < 4; j++) {
            int idx = tid * 4 + j;
            int mr = idx >> 5, c4 = idx & 31;
            *(float4*)&As[mr][c4 * 4] = *(const float4*)(Tb + (size_t)(m0 + mr) * NQ + n0 + c4 * 4);
        }
#pragma unroll
        for (int j = 0; j < 4; j++) {
            int idx = tid * 4 + j;
            int mr = idx >> 5, c4 = idx & 31;
            *(float4*)&Bs[mr][c4 * 4] = *(const float4*)(Vb + (size_t)(m0 + mr) * CC + c0 + c4 * 4);
        }
        __syncthreads();
#pragma unroll
        for (int kk = 0; kk < BKT; kk++) {
            float a[8], bb[8];
            *(float4*)a        = *(const float4*)&As[kk][ty * 8];
            *(float4*)(a + 4)  = *(const float4*)&As[kk][ty * 8 + 4];
            *(float4*)bb       = *(const float4*)&Bs[kk][tx * 8];
            *(float4*)(bb + 4) = *(const float4*)&Bs[kk][tx * 8 + 4];
#pragma unroll
            for (int i = 0; i < 8; i++)
#pragma unroll
                for (int jj = 0; jj < 8; jj++)
                    acc[i][jj] = fmaf(a[i], bb[jj], acc[i][jj]);
        }
        __syncthreads();
    }
#pragma unroll
    for (int i = 0; i < 8; i++) {
        int n = n0 + ty * 8 + i;
        float* xr = X + (size_t)(n * BB + b) * CC + c0 + tx * 8;
        float4 o0, o1;
        o0.x = acc[i][0]; o0.y = acc[i][1]; o0.z = acc[i][2]; o0.w = acc[i][3];
        o1.x = acc[i][4]; o1.y = acc[i][5]; o1.z = acc[i][6]; o1.w = acc[i][7];
        *(float4*)xr = o0; *(float4*)(xr + 4) = o1;
    }
}

// ---------------- small kernels ----------------
__global__ void __launch_bounds__(128) l2norm_split(
    const float* __restrict__ X, __nv_bfloat16* __restrict__ H, __nv_bfloat16* __restrict__ L)
{
    const int r = blockIdx.x;
    const float* row = X + (size_t)r * CC;
    float v[5];
    float ss = 0.0f;
#pragma unroll
    for (int i = 0; i < 5; i++) { v[i] = row[threadIdx.x + i * 128]; ss = fmaf(v[i], v[i], ss); }
    for (int o = 16; o; o >>= 1) ss += __shfl_down_sync(0xffffffffu, ss, o);
    __shared__ float ws[4];
    if ((threadIdx.x & 31) == 0) ws[threadIdx.x >> 5] = ss;
    __syncthreads();
    float tot = ws[0] + ws[1] + ws[2] + ws[3];
    float inv = 1.0f / fmaxf(sqrtf(tot), 1e-12f);
#pragma unroll
    for (int i = 0; i < 5; i++) {
        float y = v[i] * inv;
        __nv_bfloat16 h = __float2bfloat16(y);
        __nv_bfloat16 l = __float2bfloat16(y - __bfloat162float(h));
        H[(size_t)r * CC + threadIdx.x + i * 128] = h;
        L[(size_t)r * CC + threadIdx.x + i * 128] = l;
    }
}

// compact active rows, counts, mu; zero attn; reset barrier; zero Tc/Vc pad rows.
__global__ void __launch_bounds__(256) init_rows(
    const void* __restrict__ mask, const int* __restrict__ mode,
    int* __restrict__ rowlist, int* __restrict__ cnt,
    float* __restrict__ mu, float* __restrict__ attn_out,
    float* __restrict__ Tc, float* __restrict__ Vc)
{
    const int w = threadIdx.x >> 5, lane = threadIdx.x & 31;
    const int md = *mode;
    const int b = w;
    int base = 0;
    for (int c = 0; c < 32; c++) {
        int m = c * 32 + lane;
        bool act = mget(mask, (b << 10) + m, md);
        unsigned bal = __ballot_sync(0xffffffffu, act);
        int pre = __popc(bal & ((1u << lane) - 1u));
        if (act) rowlist[(b << 10) + base + pre] = m;
        base += __popc(bal);
    }
    if (lane == 0) {
        cnt[b] = base;
        int cm = base > 1 ? base : 1;
        mu[b] = 1.0f / (float)cm + 1e-8f;
    }
    // zero pad rows [cnt, round32(cnt)) of Tc and Vc for this batch
    {
        int cpad = (base + 31) & ~31;
        for (int rr = base; rr < cpad && rr < MM; rr++) {
            float* tr = Tc + ((size_t)(b * MM + rr) << 10);
            for (int c = lane; c < NQ; c += 32) tr[c] = 0.0f;
            float* vr = Vc + (size_t)(b * MM + rr) * CC;
            for (int c = lane; c < CC; c += 32) vr[c] = 0.0f;
        }
    }
    if (threadIdx.x == 0) g_bar_cnt = 0u;
    for (int i = threadIdx.x; i < ROWS; i += 256) attn_out[i] = 0.0f;
}

// Vc[b][i][:] = V[b][rowlist[b][i]][:]
__global__ void __launch_bounds__(128) gather_v(
    const float* __restrict__ V, const int* __restrict__ rowlist,
    const int* __restrict__ cntv, float* __restrict__ Vc)
{
    const int idx = blockIdx.x;
    const int b = idx >> 10, i = idx & 1023;
    if (i >= cntv[b]) return;
    const int m = rowlist[(b << 10) + i];
    const float4* src = (const float4*)(V + (size_t)(b * MM + m) * CC);
    float4* dst = (float4*)(Vc + (size_t)(b * MM + i) * CC);
    for (int t = threadIdx.x; t < CC / 4; t += 128) dst[t] = src[t];
}

// ---------------- persistent Sinkhorn ----------------
__device__ __forceinline__ void gridbar(int tid, unsigned epoch)
{
    __syncthreads();
    if (tid == 0) {
        __threadfence();
        atomicAdd(&g_bar_cnt, 1u);
        const unsigned tgt = (unsigned)NBLK * epoch;
        while (*(volatile unsigned*)&g_bar_cnt < tgt) __nanosleep(32);
        __threadfence();
    }
    __syncthreads();
}

__global__ void __launch_bounds__(SK_THREADS, 1) sk_persist(
    const float* __restrict__ E, const float* __restrict__ sim,
    float* __restrict__ Tc, float* __restrict__ attn_out, float nu_eff)
{
    extern __shared__ float smemf[];
    float* e_s   = smemf;
    float* acc_s = smemf + ROWCAP * 1024;
    float* a_s   = acc_s + 8 * 1024;
    int*   rows_s = (int*)(a_s + 64);

    const int tid = threadIdx.x;
    const int w = tid >> 5, lane = tid & 31;
    const int b = blockIdx.x / BPB;
    const int j = blockIdx.x % BPB;
    const int cnt = g_cnt[b];
    const int r0 = j * cnt / BPB;
    const int r1 = (j + 1) * cnt / BPB;
    const int nrows = r1 - r0;
    const int ncache = nrows < ROWCAP ? nrows : ROWCAP;
    const float mub = g_mu[b];

    for (int i = tid; i < nrows; i += SK_THREADS)
        rows_s[i] = g_rowlist[(b << 10) + r0 + i];
    __syncthreads();

    for (int i = 0; i < ncache; i++) {
        const float4* src = (const float4*)(E + ((size_t)b << 20) + ((size_t)rows_s[i] << 10));
        float4* dst = (float4*)(e_s + i * 1024);
        for (int t = tid; t < 256; t += SK_THREADS) dst[t] = __ldg(src + t);
    }
    __syncthreads();

    float4 bvreg[8];
#pragma unroll
    for (int t = 0; t < 8; t++) bvreg[t] = make_float4(1.f, 1.f, 1.f, 1.f);

    for (int it = 0; it < 100; it++) {
        const int par = it & 1;
        float4 cacc[8] = {};
        for (int i = w; i < nrows; i += 8) {
            const float4* er = (i < ncache)
                ? (const float4*)(e_s + i * 1024)
                : (const float4*)(E + ((size_t)b << 20) + ((size_t)rows_s[i] << 10));
            float4 e[8];
            float s = 0.0f;
#pragma unroll
            for (int t = 0; t < 8; t++) {
                e[t] = er[t * 32 + lane];
                s = fmaf(e[t].x, bvreg[t].x, s); s = fmaf(e[t].y, bvreg[t].y, s);
                s = fmaf(e[t].z, bvreg[t].z, s); s = fmaf(e[t].w, bvreg[t].w, s);
            }
#pragma unroll
            for (int o = 16; o; o >>= 1) s += __shfl_xor_sync(0xffffffffu, s, o);
            float av = (s > 0.0f) ? mub / s : 0.0f;
            if (lane == 0) a_s[i] = av;
#pragma unroll
            for (int t = 0; t < 8; t++) {
                cacc[t].x = fmaf(av, e[t].x, cacc[t].x);
                cacc[t].y = fmaf(av, e[t].y, cacc[t].y);
                cacc[t].z = fmaf(av, e[t].z, cacc[t].z);
                cacc[t].w = fmaf(av, e[t].w, cacc[t].w);
            }
        }
#pragma unroll
        for (int t = 0; t < 8; t++)
            *(float4*)&acc_s[w * 1024 + t * 128 + lane * 4] = cacc[t];
        __syncthreads();
        {
            float4 ssum = *(const float4*)&acc_s[tid * 4];
#pragma unroll
            for (int ww = 1; ww < 8; ww++) {
                float4 v = *(const float4*)&acc_s[ww * 1024 + tid * 4];
                ssum.x += v.x; ssum.y += v.y; ssum.z += v.z; ssum.w += v.w;
            }
            *(float4*)&g_part[par][(size_t)blockIdx.x * 1024 + tid * 4] = ssum;
        }
        gridbar(tid, (unsigned)(it + 1));
        {
            const float* pp = &g_part[par][(size_t)(b * BPB) * 1024];
            const int c4 = tid * 4;
            float4 c = __ldcg((const float4*)(pp + c4));
#pragma unroll
            for (int jj = 1; jj < BPB; jj++) {
                float4 v = __ldcg((const float4*)(pp + jj * 1024 + c4));
                c.x += v.x; c.y += v.y; c.z += v.z; c.w += v.w;
            }
            float4 bv4;
            bv4.x = (c.x > 0.0f) ? nu_eff / c.x : 0.0f;
            bv4.y = (c.y > 0.0f) ? nu_eff / c.y : 0.0f;
            bv4.z = (c.z > 0.0f) ? nu_eff / c.z : 0.0f;
            bv4.w = (c.w > 0.0f) ? nu_eff / c.w : 0.0f;
            *(float4*)&acc_s[c4] = bv4;
        }
        __syncthreads();
#pragma unroll
        for (int t = 0; t < 8; t++)
            bvreg[t] = *(const float4*)&acc_s[t * 128 + lane * 4];
        __syncthreads();
    }

    // finalize: write COMPACTED T (slot = r0+i) and attn (by original row m)
    for (int i = w; i < nrows; i += 8) {
        const int m = rows_s[i];
        const size_t sbase = ((size_t)b << 20) + ((size_t)m << 10);
        const float av = a_s[i];
        const float4* er = (i < ncache)
            ? (const float4*)(e_s + i * 1024)
            : (const float4*)(E + sbase);
        const float4* sr = (const float4*)(sim + sbase);
        float4* tw = (float4*)(Tc + ((size_t)(b * MM + r0 + i) << 10));
        float s = 0.0f;
#pragma unroll
        for (int t = 0; t < 8; t++) {
            float4 e = er[t * 32 + lane];
            float4 bb = bvreg[t];
            float4 T4;
            T4.x = av * e.x * bb.x; T4.y = av * e.y * bb.y;
            T4.z = av * e.z * bb.z; T4.w = av * e.w * bb.w;
            tw[t * 32 + lane] = T4;
            float4 sv = __ldg(sr + t * 32 + lane);
            s = fmaf(sv.x, T4.x, s); s = fmaf(sv.y, T4.y, s);
            s = fmaf(sv.z, T4.z, s); s = fmaf(sv.w, T4.w, s);
        }
#pragma unroll
        for (int o = 16; o; o >>= 1) s += __shfl_xor_sync(0xffffffffu, s, o);
        if (lane == 0) attn_out[(b << 10) + m] = SCORE_SCALE * s;
    }
}

// ---------------- launch ----------------
extern "C" void kernel_launch(void* const* d_in, const int* in_sizes, int n_in,
                              void* d_out, int out_size)
{
    const float* xq = (const float*)d_in[0];
    const float* xk = (const float*)d_in[1];
    const float* xv = (const float*)d_in[2];
    const void*  mask = d_in[3];
    const float* Wq = (const float*)d_in[4];
    const float* bq = (const float*)d_in[5];
    const float* Wk = (const float*)d_in[6];
    const float* bk = (const float*)d_in[7];
    const float* Wv = (const float*)d_in[8];
    const float* bv_in = (const float*)d_in[9];
    const float* Wp = (const float*)d_in[10];
    const float* bp = (const float*)d_in[11];
    float* out = (float*)d_out;

    float *p_q, *p_k, *p_v, *p_x, *p_sim, *p_E, *p_Tc, *p_vc, *p_mu, *p_sink;
    int *p_mode, *p_rows, *p_cnt;
    __nv_bfloat16 *p_ah, *p_al, *p_wh, *p_wl, *p_qh, *p_ql, *p_kh, *p_kl;
    cudaGetSymbolAddress((void**)&p_q, g_q);
    cudaGetSymbolAddress((void**)&p_k, g_k);
    cudaGetSymbolAddress((void**)&p_v, g_v);
    cudaGetSymbolAddress((void**)&p_x, g_x);
    cudaGetSymbolAddress((void**)&p_sim, g_sim);
    cudaGetSymbolAddress((void**)&p_E, g_E);
    cudaGetSymbolAddress((void**)&p_Tc, g_Tc);
    cudaGetSymbolAddress((void**)&p_vc, g_vc);
    cudaGetSymbolAddress((void**)&p_mu, g_mu);
    cudaGetSymbolAddress((void**)&p_sink, g_attn_sink);
    cudaGetSymbolAddress((void**)&p_mode, g_mode);
    cudaGetSymbolAddress((void**)&p_rows, g_rowlist);
    cudaGetSymbolAddress((void**)&p_cnt, g_cnt);
    cudaGetSymbolAddress((void**)&p_ah, g_ah);
    cudaGetSymbolAddress((void**)&p_al, g_al);
    cudaGetSymbolAddress((void**)&p_wh, g_wh);
    cudaGetSymbolAddress((void**)&p_wl, g_wl);
    cudaGetSymbolAddress((void**)&p_qh, g_qh);
    cudaGetSymbolAddress((void**)&p_ql, g_ql);
    cudaGetSymbolAddress((void**)&p_kh, g_kh);
    cudaGetSymbolAddress((void**)&p_kl, g_kl);

    cudaFuncSetAttribute(sk_persist, cudaFuncAttributeMaxDynamicSharedMemorySize, SK_SMEM_BYTES);

    float* attn_out = (out_size >= NQ * BB * CC + BB * MM) ? (out + NQ * BB * CC) : p_sink;

    detect_mask_kernel<<<1, 256>>>((const unsigned int*)mask, p_mode);

    const int NA = ROWS * CC;          // 5,242,880
    const int NW = CC * CC;            // 409,600
    dim3 gbf(CC / 128, ROWS / 128);    // (5, 64)

    // Q projection
    split_bf16<<<NA / 1024, 256>>>(xq, p_ah, p_al, NA);
    split_bf16<<<NW / 1024, 256>>>(Wq, p_wh, p_wl, NW);
    mmagemm_nt_bias<<<gbf, 256>>>(p_ah, p_al, p_wh, p_wl, bq, p_q);
    // K projection
    split_bf16<<<NA / 1024, 256>>>(xk, p_ah, p_al, NA);
    split_bf16<<<NW / 1024, 256>>>(Wk, p_wh, p_wl, NW);
    mmagemm_nt_bias<<<gbf, 256>>>(p_ah, p_al, p_wh, p_wl, bk, p_k);
    // V projection
    split_bf16<<<NA / 1024, 256>>>(xv, p_ah, p_al, NA);
    split_bf16<<<NW / 1024, 256>>>(Wv, p_wh, p_wl, NW);
    mmagemm_nt_bias<<<gbf, 256>>>(p_ah, p_al, p_wh, p_wl, bv_in, p_v);

    // normalize + split q/k to bf16 hi/lo
    l2norm_split<<<ROWS, 128>>>(p_q, p_qh, p_ql);
    l2norm_split<<<ROWS, 128>>>(p_k, p_kh, p_kl);

    init_rows<<<1, 256>>>(mask, p_mode, p_rows, p_cnt, p_mu, attn_out, p_Tc, p_vc);
    gather_v<<<ROWS, 128>>>(p_v, p_rows, p_cnt, p_vc);

    dim3 gsim(NQ / 128, MM / 128, BB);  // (8, 8, 8)
    mmagemm_sim<<<gsim, 256>>>(p_kh, p_kl, p_qh, p_ql, mask, p_mode, p_sim, p_E);

    const float nu_eff = 1.0f / (float)NQ + 1e-8f;
    sk_persist<<<NBLK, SK_THREADS, SK_SMEM_BYTES>>>(p_E, p_sim, p_Tc, attn_out, nu_eff);

    dim3 gx(CC / BNT, NQ / BMT, BB);    // (5, 8, 8)
    gemm_tn_x<<<gx, 256>>>(p_Tc, p_vc, p_cnt, p_x);

    // output projection
    split_bf16<<<NA / 1024, 256>>>(p_x, p_ah, p_al, NA);
    split_bf16<<<NW / 1024, 256>>>(Wp, p_wh, p_wl, NW);
    mmagemm_nt_bias<<<gbf, 256>>>(p_ah, p_al, p_wh, p_wl, bp, out);
}